// round 3
// baseline (speedup 1.0000x reference)
#include <cuda_runtime.h>
#include <math.h>

#define NQ 8
#define NS 256          // 2^8 amplitudes
#define DEPTH 200
#define BSZ 16384
#define NXF 64
#define NT 32           // batches per block in main kernel
#define NTP 33          // padded batch stride in shared
#define NBLK (BSZ/NT)   // 512 blocks

typedef unsigned long long ull;

// ---------------- device globals (no cudaMalloc allowed) ----------------
__device__ float4 g_uv[600 * 8];     // per layer, per qubit: (u.re,u.im,v.re,v.im) of RY(b)*RX(a)
__device__ float4 g_g4[600 * 4 * 16];// fused 2-qubit 4x4 gate entries, packed (Mr,Mr,-Mi,Mi)
__device__ float2 g_encphi[128];     // (cos(phi/2), sin(phi/2)) for the 2*64 encode phi angles
__device__ float2 g_v0[NS];          // U1 |0>
__device__ float2 g_U2T[NS * NS];    // [k][m] = (U2*Dcz)[m][k]
__device__ float2 g_U3T[NS * NS];    // [k][m] = (U3*Dcz)[m][k]

// ---------------- packed f32x2 helpers (Blackwell FFMA2 path) ----------------
__device__ __forceinline__ void ffma2(ull& d, ull a, ull b) {
    asm("fma.rn.f32x2 %0, %1, %2, %0;" : "+l"(d) : "l"(a), "l"(b));
}
__device__ __forceinline__ void fmul2(ull& d, ull a) {
    asm("mul.rn.f32x2 %0, %0, %1;" : "+l"(d) : "l"(a));
}
__device__ __forceinline__ ull pack2(float lo, float hi) {
    ull r; asm("mov.b64 %0, {%1, %2};" : "=l"(r) : "f"(lo), "f"(hi)); return r;
}

// ring-CZ parity sign for amplitude index n (qubit i <-> bit 7-i)
__device__ __forceinline__ float czsign(int n) {
    int par = __popc(n & (n >> 1)) + ((n & (n >> 7)) & 1);
    return (par & 1) ? -1.0f : 1.0f;
}

// ---------------- K0: angle tables (grid-strided) ----------------
__global__ void k_tables(const float* __restrict__ phi) {
    int tid = blockIdx.x * blockDim.x + threadIdx.x;
    int stride = gridDim.x * blockDim.x;
    for (int idx = tid; idx < 600 * 8; idx += stride) {
        int L = idx >> 3, q = idx & 7;
        int base, l;
        if (L < 200)      { base = 0;    l = L; }
        else if (L < 400) { base = 3264; l = L - 200; }
        else              { base = 6528; l = L - 400; }
        float a = phi[base + l * 16 + q];
        float b = phi[base + l * 16 + 8 + q];
        float ca, sa, cb, sb;
        sincosf(0.5f * a, &sa, &ca);
        sincosf(0.5f * b, &sb, &cb);
        g_uv[idx] = make_float4(ca * cb, sa * sb, ca * sb, -sa * cb);
    }
    for (int idx = tid; idx < 128; idx += stride) {
        int base = (idx < 64) ? 3200 : 6400;
        float p = phi[base + idx];
        float c, s;
        sincosf(0.5f * p, &s, &c);
        g_encphi[idx] = make_float2(c, s);
    }
}

// M = [[u, -conj(v)],[v, conj(u)]] entry (r,c) from uv=(ur,ui,vr,vi)
__device__ __forceinline__ float2 mentry(float4 uv, int r, int c) {
    if (r == 0 && c == 0) return make_float2( uv.x,  uv.y);
    if (r == 0 && c == 1) return make_float2(-uv.z,  uv.w);
    if (r == 1 && c == 0) return make_float2( uv.z,  uv.w);
    return                       make_float2( uv.x, -uv.y);
}

// ---------------- K0b: fused 2-qubit 4x4 gates ----------------
__global__ void k_tables2() {
    int idx = blockIdx.x * blockDim.x + threadIdx.x;
    if (idx >= 600 * 4 * 16) return;
    int e  = idx & 15;
    int gi = (idx >> 4) & 3;
    int L  = idx >> 6;
    int row = e >> 2, col = e & 3;
    float4 uvh = g_uv[L * 8 + 2 * gi];       // qubit 2*gi   (hi bit of pair)
    float4 uvl = g_uv[L * 8 + 2 * gi + 1];   // qubit 2*gi+1 (lo bit of pair)
    float2 mh = mentry(uvh, row >> 1, col >> 1);
    float2 ml = mentry(uvl, row & 1,  col & 1);
    float mr = mh.x * ml.x - mh.y * ml.y;
    float mi = mh.x * ml.y + mh.y * ml.x;
    g_g4[idx] = make_float4(mr, mr, -mi, mi);
}

// ---------------- K1: build v0, U2', U3' columns (2-qubit fused gates) ----------------
__global__ void __launch_bounds__(128) k_build() {
    __shared__ float2 st[NS];
    int t = threadIdx.x;           // 0..127
    int blk = blockIdx.x;

    int Lbase, col;
    bool lastCZ;
    float2* outp;
    float initv;
    if (blk < 256)      { Lbase = 200; lastCZ = true;  col = blk;       outp = &g_U2T[col * NS]; initv = czsign(col); }
    else if (blk < 512) { Lbase = 400; lastCZ = false; col = blk - 256; outp = &g_U3T[col * NS]; initv = czsign(col); }
    else                { Lbase = 0;   lastCZ = true;  col = 0;         outp = g_v0;             initv = 1.0f; }

    st[t]       = make_float2(0.f, 0.f);
    st[t + 128] = make_float2(0.f, 0.f);
    __syncthreads();
    if (t == 0) st[col] = make_float2(initv, 0.f);

    ull s0 = pack2(czsign(2 * t), czsign(2 * t));           // row 2h   at i==3 is amp 2t
    ull s1 = pack2(czsign(2 * t + 1), czsign(2 * t + 1));   // row 2h+1 at i==3 is amp 2t+1
    int g = t >> 1, h = t & 1;
    __syncthreads();

    for (int l = 0; l < DEPTH; l++) {
        bool cz = (l < DEPTH - 1) || lastCZ;
        #pragma unroll
        for (int i = 0; i < 4; i++) {
            int pl = 6 - 2 * i;                 // pair occupies bits (pl+1, pl)
            int low = (1 << pl) - 1;
            int base = ((g >> pl) << (pl + 2)) | (g & low);
            float2 a0 = st[base];
            float2 a1 = st[base | (1 << pl)];
            float2 a2 = st[base | (2 << pl)];
            float2 a3 = st[base | (3 << pl)];
            ull ap[4], as[4];
            ap[0] = pack2(a0.x, a0.y); as[0] = pack2(a0.y, a0.x);
            ap[1] = pack2(a1.x, a1.y); as[1] = pack2(a1.y, a1.x);
            ap[2] = pack2(a2.x, a2.y); as[2] = pack2(a2.y, a2.x);
            ap[3] = pack2(a3.x, a3.y); as[3] = pack2(a3.y, a3.x);
            const float4* Mrow = &g_g4[(((Lbase + l) * 4 + i) << 4) + (h << 3)];
            ull acc0 = 0ull, acc1 = 0ull;
            #pragma unroll
            for (int c = 0; c < 4; c++) {
                ulonglong2 m0 = *reinterpret_cast<const ulonglong2*>(&Mrow[c]);
                ffma2(acc0, m0.x, ap[c]);
                ffma2(acc0, m0.y, as[c]);
            }
            #pragma unroll
            for (int c = 0; c < 4; c++) {
                ulonglong2 m1 = *reinterpret_cast<const ulonglong2*>(&Mrow[4 + c]);
                ffma2(acc1, m1.x, ap[c]);
                ffma2(acc1, m1.y, as[c]);
            }
            if (i == 3 && cz) { fmul2(acc0, s0); fmul2(acc1, s1); }
            __syncwarp();
            *reinterpret_cast<ull*>(&st[base | ((2 * h)     << pl)]) = acc0;
            *reinterpret_cast<ull*>(&st[base | ((2 * h + 1) << pl)]) = acc1;
            __syncthreads();
        }
    }
    outp[t] = st[t];
    outp[t + 128] = st[t + 128];
}

// ---------------- K2: fused per-batch pipeline ----------------
__device__ __forceinline__ void su2_mul(float& Eur, float& Eui, float& Evr, float& Evi,
                                        float gur, float gui, float gvr, float gvi) {
    float ur = gur * Eur - gui * Eui - (gvr * Evr + gvi * Evi);
    float ui = gur * Eui + gui * Eur - (gvr * Evi - gvi * Evr);
    float vr = gvr * Eur - gvi * Eui + (gur * Evr + gui * Evi);
    float vi = gvr * Eui + gvi * Eur + (gur * Evi - gui * Evr);
    Eur = ur; Eui = ui; Evr = vr; Evi = vi;
}

__device__ __forceinline__ float4 compose_E(const float* __restrict__ x, int bg,
                                            int xoff, int enc, int i) {
    float Eur = 1.f, Eui = 0.f, Evr = 0.f, Evi = 0.f;
    #pragma unroll
    for (int j = 0; j < 4; j++) {
        float2 p0 = g_encphi[enc * 64 + 8 * i + 2 * j];
        float2 p1 = g_encphi[enc * 64 + 8 * i + 2 * j + 1];
        float xv = x[(size_t)bg * NXF + xoff + 4 * i + j];
        float sx, cx;
        sincosf(0.5f * xv, &sx, &cx);
        if ((j & 1) == 0) {
            su2_mul(Eur, Eui, Evr, Evi, p0.x, 0.f, p0.y, 0.f);   // RY(p0)
            su2_mul(Eur, Eui, Evr, Evi, cx, 0.f, 0.f, -sx);      // RX(x)
            su2_mul(Eur, Eui, Evr, Evi, p1.x, 0.f, p1.y, 0.f);   // RY(p1)
        } else {
            su2_mul(Eur, Eui, Evr, Evi, p0.x, 0.f, 0.f, -p0.y);  // RX(p0)
            su2_mul(Eur, Eui, Evr, Evi, cx, 0.f, sx, 0.f);       // RY(x)
            su2_mul(Eur, Eui, Evr, Evi, p1.x, 0.f, 0.f, -p1.y);  // RX(p1)
        }
    }
    return make_float4(Eur, Eui, Evr, Evi);
}

__device__ __forceinline__ void apply_gates(float2* sPsi, const float4* sE, int tid) {
    #pragma unroll
    for (int q = 0; q < 8; q++) {
        int p = 7 - q;
        int low = (1 << p) - 1;
        #pragma unroll
        for (int it = 0; it < (128 * NT) / 256; it++) {  // 16
            int task = tid + it * 256;
            int b = task & (NT - 1);
            int pr = task >> 5;
            int n0 = ((pr & ~low) << 1) | (pr & low);
            int n1 = n0 | (1 << p);
            float4 E = sE[q * NT + b];
            float2 a0 = sPsi[n0 * NTP + b];
            float2 a1 = sPsi[n1 * NTP + b];
            float2 b0, b1;
            b0.x = E.x * a0.x - E.y * a0.y - (E.z * a1.x + E.w * a1.y);
            b0.y = E.x * a0.y + E.y * a0.x - (E.z * a1.y - E.w * a1.x);
            b1.x = E.z * a0.x - E.w * a0.y + (E.x * a1.x + E.y * a1.y);
            b1.y = E.z * a0.y + E.w * a0.x + (E.x * a1.y - E.y * a1.x);
            sPsi[n0 * NTP + b] = b0;
            sPsi[n1 * NTP + b] = b1;
        }
        __syncthreads();
    }
}

// in-place complex GEMM using packed f32x2 FMAs, warp tile = (m-half, b-octet):
//   sPsi[m][b] = sum_k AT[k][m] * sPsi[k][b]
// A staged into shared pre-expanded as (a.r, a.i, -a.i, a.r); LDS.128 per thread
// fetches only r=4 rows per kk (halved crossbar traffic vs r=8/j=4 tiling).
__device__ __forceinline__ void do_gemm(float2* sPsi, float4* sA4,
                                        const float2* __restrict__ AT,
                                        int tid, int lane, int warp) {
    int mh = warp >> 2;            // m-half:   m = mh*128 + 32r + lane
    int bo = warp & 3;             // b-octet:  b = bo*8 + j
    ull acc[4][8];
    #pragma unroll
    for (int r = 0; r < 4; r++)
        #pragma unroll
        for (int j = 0; j < 8; j++) acc[r][j] = 0ull;

    float2 pre[8];
    #pragma unroll
    for (int r = 0; r < 8; r++) pre[r] = AT[tid + r * 256];   // kc = 0 prefetch

    for (int kc = 0; kc < 32; kc++) {
        __syncthreads();  // previous compute done reading sA4
        #pragma unroll
        for (int r = 0; r < 8; r++) {
            float2 v = pre[r];
            sA4[tid + r * 256] = make_float4(v.x, v.y, -v.y, v.x);
        }
        __syncthreads();
        if (kc + 1 < 32) {
            #pragma unroll
            for (int r = 0; r < 8; r++) pre[r] = AT[(kc + 1) * 2048 + tid + r * 256];
        }
        #pragma unroll
        for (int kk = 0; kk < 8; kk++) {
            int k = kc * 8 + kk;
            ulonglong2 av[4];
            #pragma unroll
            for (int r = 0; r < 4; r++)
                av[r] = *reinterpret_cast<const ulonglong2*>(&sA4[kk * 256 + mh * 128 + 32 * r + lane]);
            #pragma unroll
            for (int j = 0; j < 8; j++) {
                float2 bv = sPsi[k * NTP + bo * 8 + j];
                ull Br = pack2(bv.x, bv.x);
                ull Bi = pack2(bv.y, bv.y);
                #pragma unroll
                for (int r = 0; r < 4; r++) {
                    ffma2(acc[r][j], av[r].x, Br);   // (a.r,a.i) * (b.r,b.r)
                    ffma2(acc[r][j], av[r].y, Bi);   // (-a.i,a.r) * (b.i,b.i)
                }
            }
        }
    }
    __syncthreads();  // all reads of sPsi done before overwrite
    #pragma unroll
    for (int r = 0; r < 4; r++)
        #pragma unroll
        for (int j = 0; j < 8; j++)
            *reinterpret_cast<ull*>(&sPsi[(mh * 128 + 32 * r + lane) * NTP + bo * 8 + j]) = acc[r][j];
    __syncthreads();
}

__global__ void __launch_bounds__(256, 2) k_main(const float* __restrict__ x,
                                                 float* __restrict__ out) {
    extern __shared__ float smraw[];
    float2* sPsi = (float2*)smraw;              // NS * NTP         (67584 B)
    float4* sA4  = (float4*)(sPsi + NS * NTP);  // 8 * 256 float4   (32768 B)
    float4* sE   = sA4 + 8 * NS;                // 8 * NT float4    ( 4096 B)

    int tid = threadIdx.x;
    int lane = tid & 31, warp = tid >> 5;       // 8 warps
    int bbase = blockIdx.x * NT;

    // ---- E1 compose: tid -> (b = tid&31, i = tid>>5) ----
    {
        int b = tid & (NT - 1), i = tid >> 5;
        sE[i * NT + b] = compose_E(x, bbase + b, 0, 0, i);
    }
    // ---- init Psi = v0 (broadcast over batches) ----
    for (int idx = tid; idx < NS * NT; idx += 256) {
        int b = idx & (NT - 1), amp = idx >> 5;
        sPsi[amp * NTP + b] = g_v0[amp];
    }
    __syncthreads();

    apply_gates(sPsi, sE, tid);                 // encode 1 (CZ folded into U2')
    do_gemm(sPsi, sA4, g_U2T, tid, lane, warp);

    // ---- E2 compose ----
    {
        int b = tid & (NT - 1), i = tid >> 5;
        sE[i * NT + b] = compose_E(x, bbase + b, 32, 1, i);
    }
    __syncthreads();

    apply_gates(sPsi, sE, tid);                 // encode 2 (CZ folded into U3')
    do_gemm(sPsi, sA4, g_U3T, tid, lane, warp);

    // ---- measurement: warp w handles batches w*4..w*4+3 ----
    for (int j = 0; j < 4; j++) {
        int b = warp * 4 + j;
        float sums[8];
        #pragma unroll
        for (int k = 0; k < 8; k++) sums[k] = 0.f;
        #pragma unroll
        for (int r = 0; r < 8; r++) {
            int m = lane + 32 * r;
            float2 ps = sPsi[m * NTP + b];
            float p2 = ps.x * ps.x + ps.y * ps.y;
            sums[4] += (m & 128) ? -p2 : p2;   // Z q0
            sums[5] += (m & 64)  ? -p2 : p2;   // Z q1
            sums[6] += (m & 32)  ? -p2 : p2;   // Z q2
            sums[7] += (m & 16)  ? -p2 : p2;   // Z q3
            float2 q0 = sPsi[(m ^ 128) * NTP + b];
            sums[0] += ps.x * q0.x + ps.y * q0.y;   // X q0
            float2 q1 = sPsi[(m ^ 64) * NTP + b];
            sums[1] += ps.x * q1.x + ps.y * q1.y;   // X q1
            float2 q2 = sPsi[(m ^ 32) * NTP + b];
            sums[2] += ps.x * q2.x + ps.y * q2.y;   // X q2
            float2 q3 = sPsi[(m ^ 16) * NTP + b];
            sums[3] += ps.x * q3.x + ps.y * q3.y;   // X q3
        }
        #pragma unroll
        for (int off = 16; off; off >>= 1) {
            #pragma unroll
            for (int k = 0; k < 8; k++)
                sums[k] += __shfl_xor_sync(0xffffffffu, sums[k], off);
        }
        if (lane < 8) out[(size_t)(bbase + b) * 8 + lane] = sums[lane];
    }
}

// ---------------- launch ----------------
extern "C" void kernel_launch(void* const* d_in, const int* in_sizes, int n_in,
                              void* d_out, int out_size) {
    const float* x   = (const float*)d_in[0];
    const float* phi = (const float*)d_in[1];
    float* out = (float*)d_out;

    const size_t smem = (size_t)(NS * NTP) * sizeof(float2)   // 67584
                      + (size_t)(8 * NS) * sizeof(float4)     // 32768
                      + (size_t)(8 * NT) * sizeof(float4);    //  4096
    cudaFuncSetAttribute(k_main, cudaFuncAttributeMaxDynamicSharedMemorySize, (int)smem);

    k_tables<<<20, 256>>>(phi);
    k_tables2<<<150, 256>>>();
    k_build<<<513, 128>>>();
    k_main<<<NBLK, 256, smem>>>(x, out);
}

// round 4
// speedup vs baseline: 1.2729x; 1.2729x over previous
#include <cuda_runtime.h>
#include <math.h>

#define NQ 8
#define NS 256          // 2^8 amplitudes
#define DEPTH 200
#define BSZ 16384
#define NXF 64
#define NT 32           // batches per block in main kernel
#define NTP 33          // padded batch stride in shared
#define NBLK (BSZ/NT)   // 512 blocks

typedef unsigned long long ull;

// ---------------- device globals (no cudaMalloc allowed) ----------------
__device__ float4 g_uv[600 * 8];     // per layer, per qubit: (u.re,u.im,v.re,v.im) of RY(b)*RX(a)
__device__ float4 g_g4[600 * 4 * 16];// fused 2-qubit 4x4 gate entries, packed (Mr,Mr,-Mi,Mi)
__device__ float2 g_encphi[128];     // (cos(phi/2), sin(phi/2)) for the 2*64 encode phi angles
__device__ float2 g_v0[NS];          // U1 |0>
__device__ float2 g_U2T[NS * NS];    // [k][m] = (U2*Dcz)[m][k]
__device__ float2 g_U3T[NS * NS];    // [k][m] = (U3*Dcz)[m][k]

// ---------------- packed f32x2 helpers (Blackwell FFMA2 path) ----------------
__device__ __forceinline__ void ffma2(ull& d, ull a, ull b) {
    asm("fma.rn.f32x2 %0, %1, %2, %0;" : "+l"(d) : "l"(a), "l"(b));
}
__device__ __forceinline__ void fmul2(ull& d, ull a) {
    asm("mul.rn.f32x2 %0, %0, %1;" : "+l"(d) : "l"(a));
}
__device__ __forceinline__ ull pack2(float lo, float hi) {
    ull r; asm("mov.b64 %0, {%1, %2};" : "=l"(r) : "f"(lo), "f"(hi)); return r;
}

// ring-CZ parity sign for amplitude index n (qubit i <-> bit 7-i)
__device__ __forceinline__ float czsign(int n) {
    int par = __popc(n & (n >> 1)) + ((n & (n >> 7)) & 1);
    return (par & 1) ? -1.0f : 1.0f;
}

// ---------------- K0: angle tables (grid-strided) ----------------
__global__ void k_tables(const float* __restrict__ phi) {
    int tid = blockIdx.x * blockDim.x + threadIdx.x;
    int stride = gridDim.x * blockDim.x;
    for (int idx = tid; idx < 600 * 8; idx += stride) {
        int L = idx >> 3, q = idx & 7;
        int base, l;
        if (L < 200)      { base = 0;    l = L; }
        else if (L < 400) { base = 3264; l = L - 200; }
        else              { base = 6528; l = L - 400; }
        float a = phi[base + l * 16 + q];
        float b = phi[base + l * 16 + 8 + q];
        float ca, sa, cb, sb;
        sincosf(0.5f * a, &sa, &ca);
        sincosf(0.5f * b, &sb, &cb);
        g_uv[idx] = make_float4(ca * cb, sa * sb, ca * sb, -sa * cb);
    }
    for (int idx = tid; idx < 128; idx += stride) {
        int base = (idx < 64) ? 3200 : 6400;
        float p = phi[base + idx];
        float c, s;
        sincosf(0.5f * p, &s, &c);
        g_encphi[idx] = make_float2(c, s);
    }
}

// M = [[u, -conj(v)],[v, conj(u)]] entry (r,c) from uv=(ur,ui,vr,vi)
__device__ __forceinline__ float2 mentry(float4 uv, int r, int c) {
    if (r == 0 && c == 0) return make_float2( uv.x,  uv.y);
    if (r == 0 && c == 1) return make_float2(-uv.z,  uv.w);
    if (r == 1 && c == 0) return make_float2( uv.z,  uv.w);
    return                       make_float2( uv.x, -uv.y);
}

// ---------------- K0b: fused 2-qubit 4x4 gates ----------------
__global__ void k_tables2() {
    int idx = blockIdx.x * blockDim.x + threadIdx.x;
    if (idx >= 600 * 4 * 16) return;
    int e  = idx & 15;
    int gi = (idx >> 4) & 3;
    int L  = idx >> 6;
    int row = e >> 2, col = e & 3;
    float4 uvh = g_uv[L * 8 + 2 * gi];       // qubit 2*gi   (hi bit of pair)
    float4 uvl = g_uv[L * 8 + 2 * gi + 1];   // qubit 2*gi+1 (lo bit of pair)
    float2 mh = mentry(uvh, row >> 1, col >> 1);
    float2 ml = mentry(uvl, row & 1,  col & 1);
    float mr = mh.x * ml.x - mh.y * ml.y;
    float mi = mh.x * ml.y + mh.y * ml.x;
    g_g4[idx] = make_float4(mr, mr, -mi, mi);
}

// ---------------- K1: build v0, U2', U3' columns ----------------
// 2-qubit fused gates, staged per-layer into shared (1 KB) to avoid the
// 6.7 GB L2 storm of reading g_g4 per-thread from global.
__global__ void __launch_bounds__(128) k_build() {
    __shared__ float2 st[NS];
    __shared__ float4 sM[64];      // this layer's 4 gates x 16 packed entries
    int t = threadIdx.x;           // 0..127
    int blk = blockIdx.x;

    int Lbase, col;
    bool lastCZ;
    float2* outp;
    float initv;
    if (blk < 256)      { Lbase = 200; lastCZ = true;  col = blk;       outp = &g_U2T[col * NS]; initv = czsign(col); }
    else if (blk < 512) { Lbase = 400; lastCZ = false; col = blk - 256; outp = &g_U3T[col * NS]; initv = czsign(col); }
    else                { Lbase = 0;   lastCZ = true;  col = 0;         outp = g_v0;             initv = 1.0f; }

    st[t]       = make_float2(0.f, 0.f);
    st[t + 128] = make_float2(0.f, 0.f);
    __syncthreads();
    if (t == 0) st[col] = make_float2(initv, 0.f);

    ull s0 = pack2(czsign(2 * t), czsign(2 * t));           // row 2h   at i==3 is amp 2t
    ull s1 = pack2(czsign(2 * t + 1), czsign(2 * t + 1));   // row 2h+1 at i==3 is amp 2t+1
    int g = t >> 1, h = t & 1;
    __syncthreads();

    for (int l = 0; l < DEPTH; l++) {
        bool cz = (l < DEPTH - 1) || lastCZ;
        // stage this layer's gates (prev layer's reads fenced by its last barrier)
        if (t < 64) sM[t] = g_g4[(Lbase + l) * 64 + t];
        __syncthreads();
        #pragma unroll
        for (int i = 0; i < 4; i++) {
            int pl = 6 - 2 * i;                 // pair occupies bits (pl+1, pl)
            int low = (1 << pl) - 1;
            int base = ((g >> pl) << (pl + 2)) | (g & low);
            float2 a0 = st[base];
            float2 a1 = st[base | (1 << pl)];
            float2 a2 = st[base | (2 << pl)];
            float2 a3 = st[base | (3 << pl)];
            ull ap[4], as_[4];
            ap[0] = pack2(a0.x, a0.y); as_[0] = pack2(a0.y, a0.x);
            ap[1] = pack2(a1.x, a1.y); as_[1] = pack2(a1.y, a1.x);
            ap[2] = pack2(a2.x, a2.y); as_[2] = pack2(a2.y, a2.x);
            ap[3] = pack2(a3.x, a3.y); as_[3] = pack2(a3.y, a3.x);
            const float4* Mrow = &sM[(i << 4) + (h << 3)];
            ull acc0 = 0ull, acc1 = 0ull;
            #pragma unroll
            for (int c = 0; c < 4; c++) {
                ulonglong2 m0 = *reinterpret_cast<const ulonglong2*>(&Mrow[c]);
                ffma2(acc0, m0.x, ap[c]);
                ffma2(acc0, m0.y, as_[c]);
            }
            #pragma unroll
            for (int c = 0; c < 4; c++) {
                ulonglong2 m1 = *reinterpret_cast<const ulonglong2*>(&Mrow[4 + c]);
                ffma2(acc1, m1.x, ap[c]);
                ffma2(acc1, m1.y, as_[c]);
            }
            if (i == 3 && cz) { fmul2(acc0, s0); fmul2(acc1, s1); }
            __syncwarp();
            *reinterpret_cast<ull*>(&st[base | ((2 * h)     << pl)]) = acc0;
            *reinterpret_cast<ull*>(&st[base | ((2 * h + 1) << pl)]) = acc1;
            __syncthreads();
        }
    }
    outp[t] = st[t];
    outp[t + 128] = st[t + 128];
}

// ---------------- K2: fused per-batch pipeline ----------------
__device__ __forceinline__ void su2_mul(float& Eur, float& Eui, float& Evr, float& Evi,
                                        float gur, float gui, float gvr, float gvi) {
    float ur = gur * Eur - gui * Eui - (gvr * Evr + gvi * Evi);
    float ui = gur * Eui + gui * Eur - (gvr * Evi - gvi * Evr);
    float vr = gvr * Eur - gvi * Eui + (gur * Evr + gui * Evi);
    float vi = gvr * Eui + gvi * Eur + (gur * Evi - gui * Evr);
    Eur = ur; Eui = ui; Evr = vr; Evi = vi;
}

__device__ __forceinline__ float4 compose_E(const float* __restrict__ x, int bg,
                                            int xoff, int enc, int i) {
    float Eur = 1.f, Eui = 0.f, Evr = 0.f, Evi = 0.f;
    #pragma unroll
    for (int j = 0; j < 4; j++) {
        float2 p0 = g_encphi[enc * 64 + 8 * i + 2 * j];
        float2 p1 = g_encphi[enc * 64 + 8 * i + 2 * j + 1];
        float xv = x[(size_t)bg * NXF + xoff + 4 * i + j];
        float sx, cx;
        sincosf(0.5f * xv, &sx, &cx);
        if ((j & 1) == 0) {
            su2_mul(Eur, Eui, Evr, Evi, p0.x, 0.f, p0.y, 0.f);   // RY(p0)
            su2_mul(Eur, Eui, Evr, Evi, cx, 0.f, 0.f, -sx);      // RX(x)
            su2_mul(Eur, Eui, Evr, Evi, p1.x, 0.f, p1.y, 0.f);   // RY(p1)
        } else {
            su2_mul(Eur, Eui, Evr, Evi, p0.x, 0.f, 0.f, -p0.y);  // RX(p0)
            su2_mul(Eur, Eui, Evr, Evi, cx, 0.f, sx, 0.f);       // RY(x)
            su2_mul(Eur, Eui, Evr, Evi, p1.x, 0.f, 0.f, -p1.y);  // RX(p1)
        }
    }
    return make_float4(Eur, Eui, Evr, Evi);
}

__device__ __forceinline__ void apply_gates(float2* sPsi, const float4* sE, int tid) {
    #pragma unroll
    for (int q = 0; q < 8; q++) {
        int p = 7 - q;
        int low = (1 << p) - 1;
        #pragma unroll
        for (int it = 0; it < (128 * NT) / 256; it++) {  // 16
            int task = tid + it * 256;
            int b = task & (NT - 1);
            int pr = task >> 5;
            int n0 = ((pr & ~low) << 1) | (pr & low);
            int n1 = n0 | (1 << p);
            float4 E = sE[q * NT + b];
            float2 a0 = sPsi[n0 * NTP + b];
            float2 a1 = sPsi[n1 * NTP + b];
            float2 b0, b1;
            b0.x = E.x * a0.x - E.y * a0.y - (E.z * a1.x + E.w * a1.y);
            b0.y = E.x * a0.y + E.y * a0.x - (E.z * a1.y - E.w * a1.x);
            b1.x = E.z * a0.x - E.w * a0.y + (E.x * a1.x + E.y * a1.y);
            b1.y = E.z * a0.y + E.w * a0.x + (E.x * a1.y - E.y * a1.x);
            sPsi[n0 * NTP + b] = b0;
            sPsi[n1 * NTP + b] = b1;
        }
        __syncthreads();
    }
}

// in-place complex GEMM, packed f32x2 FMAs, warp tile = (m-half, b-octet):
//   sPsi[m][b] = sum_k AT[k][m] * sPsi[k][b]
// A staged plain (float2, 16KB); thread owns 4 consecutive m-rows so 2 LDS.128
// per kk fetch all A operands (halved crossbar traffic). Swapped operand built
// with MOVs on the ALU pipe; negation folded into the B-imag splat.
__device__ __forceinline__ void do_gemm(float2* sPsi, float2* sA2,
                                        const float2* __restrict__ AT,
                                        int tid, int lane, int warp) {
    int mh = warp >> 2;            // m-half:   m = mh*128 + lane*4 + rr
    int bo = warp & 3;             // b-octet:  b = bo*8 + j
    int mbase = mh * 128 + lane * 4;
    ull acc[4][8];
    #pragma unroll
    for (int r = 0; r < 4; r++)
        #pragma unroll
        for (int j = 0; j < 8; j++) acc[r][j] = 0ull;

    float2 pre[8];
    #pragma unroll
    for (int r = 0; r < 8; r++) pre[r] = AT[tid + r * 256];   // kc = 0 prefetch

    for (int kc = 0; kc < 32; kc++) {
        __syncthreads();  // previous compute done reading sA2
        #pragma unroll
        for (int r = 0; r < 8; r++) sA2[tid + r * 256] = pre[r];
        __syncthreads();
        if (kc + 1 < 32) {
            #pragma unroll
            for (int r = 0; r < 8; r++) pre[r] = AT[(kc + 1) * 2048 + tid + r * 256];
        }
        #pragma unroll
        for (int kk = 0; kk < 8; kk++) {
            int k = kc * 8 + kk;
            float4 a01 = *reinterpret_cast<const float4*>(&sA2[kk * 256 + mbase]);
            float4 a23 = *reinterpret_cast<const float4*>(&sA2[kk * 256 + mbase + 2]);
            ull ap[4], as_[4];
            ap[0] = pack2(a01.x, a01.y); as_[0] = pack2(a01.y, a01.x);
            ap[1] = pack2(a01.z, a01.w); as_[1] = pack2(a01.w, a01.z);
            ap[2] = pack2(a23.x, a23.y); as_[2] = pack2(a23.y, a23.x);
            ap[3] = pack2(a23.z, a23.w); as_[3] = pack2(a23.w, a23.z);
            #pragma unroll
            for (int j = 0; j < 8; j++) {
                float2 bv = sPsi[k * NTP + bo * 8 + j];
                ull Br = pack2(bv.x, bv.x);
                ull Bn = pack2(-bv.y, bv.y);
                #pragma unroll
                for (int r = 0; r < 4; r++) {
                    ffma2(acc[r][j], ap[r], Br);    // (a.r, a.i) * (b.r, b.r)
                    ffma2(acc[r][j], as_[r], Bn);   // (a.i, a.r) * (-b.i, b.i)
                }
            }
        }
    }
    __syncthreads();  // all reads of sPsi done before overwrite
    #pragma unroll
    for (int r = 0; r < 4; r++)
        #pragma unroll
        for (int j = 0; j < 8; j++)
            *reinterpret_cast<ull*>(&sPsi[(mbase + r) * NTP + bo * 8 + j]) = acc[r][j];
    __syncthreads();
}

__global__ void __launch_bounds__(256, 2) k_main(const float* __restrict__ x,
                                                 float* __restrict__ out) {
    extern __shared__ float smraw[];
    float2* sPsi = (float2*)smraw;              // NS * NTP         (67584 B)
    float2* sA2  = sPsi + NS * NTP;             // 8 * 256 float2   (16384 B)
    float4* sE   = (float4*)(sA2 + 8 * NS);     // 8 * NT float4    ( 4096 B)

    int tid = threadIdx.x;
    int lane = tid & 31, warp = tid >> 5;       // 8 warps
    int bbase = blockIdx.x * NT;

    // ---- E1 compose: tid -> (b = tid&31, i = tid>>5) ----
    {
        int b = tid & (NT - 1), i = tid >> 5;
        sE[i * NT + b] = compose_E(x, bbase + b, 0, 0, i);
    }
    // ---- init Psi = v0 (broadcast over batches) ----
    for (int idx = tid; idx < NS * NT; idx += 256) {
        int b = idx & (NT - 1), amp = idx >> 5;
        sPsi[amp * NTP + b] = g_v0[amp];
    }
    __syncthreads();

    apply_gates(sPsi, sE, tid);                 // encode 1 (CZ folded into U2')
    do_gemm(sPsi, sA2, g_U2T, tid, lane, warp);

    // ---- E2 compose ----
    {
        int b = tid & (NT - 1), i = tid >> 5;
        sE[i * NT + b] = compose_E(x, bbase + b, 32, 1, i);
    }
    __syncthreads();

    apply_gates(sPsi, sE, tid);                 // encode 2 (CZ folded into U3')
    do_gemm(sPsi, sA2, g_U3T, tid, lane, warp);

    // ---- measurement: warp w handles batches w*4..w*4+3 ----
    for (int j = 0; j < 4; j++) {
        int b = warp * 4 + j;
        float sums[8];
        #pragma unroll
        for (int k = 0; k < 8; k++) sums[k] = 0.f;
        #pragma unroll
        for (int r = 0; r < 8; r++) {
            int m = lane + 32 * r;
            float2 ps = sPsi[m * NTP + b];
            float p2 = ps.x * ps.x + ps.y * ps.y;
            sums[4] += (m & 128) ? -p2 : p2;   // Z q0
            sums[5] += (m & 64)  ? -p2 : p2;   // Z q1
            sums[6] += (m & 32)  ? -p2 : p2;   // Z q2
            sums[7] += (m & 16)  ? -p2 : p2;   // Z q3
            float2 q0 = sPsi[(m ^ 128) * NTP + b];
            sums[0] += ps.x * q0.x + ps.y * q0.y;   // X q0
            float2 q1 = sPsi[(m ^ 64) * NTP + b];
            sums[1] += ps.x * q1.x + ps.y * q1.y;   // X q1
            float2 q2 = sPsi[(m ^ 32) * NTP + b];
            sums[2] += ps.x * q2.x + ps.y * q2.y;   // X q2
            float2 q3 = sPsi[(m ^ 16) * NTP + b];
            sums[3] += ps.x * q3.x + ps.y * q3.y;   // X q3
        }
        #pragma unroll
        for (int off = 16; off; off >>= 1) {
            #pragma unroll
            for (int k = 0; k < 8; k++)
                sums[k] += __shfl_xor_sync(0xffffffffu, sums[k], off);
        }
        if (lane < 8) out[(size_t)(bbase + b) * 8 + lane] = sums[lane];
    }
}

// ---------------- launch ----------------
extern "C" void kernel_launch(void* const* d_in, const int* in_sizes, int n_in,
                              void* d_out, int out_size) {
    const float* x   = (const float*)d_in[0];
    const float* phi = (const float*)d_in[1];
    float* out = (float*)d_out;

    const size_t smem = (size_t)(NS * NTP) * sizeof(float2)   // 67584
                      + (size_t)(8 * NS) * sizeof(float2)     // 16384
                      + (size_t)(8 * NT) * sizeof(float4);    //  4096
    cudaFuncSetAttribute(k_main, cudaFuncAttributeMaxDynamicSharedMemorySize, (int)smem);

    k_tables<<<20, 256>>>(phi);
    k_tables2<<<150, 256>>>();
    k_build<<<513, 128>>>();
    k_main<<<NBLK, 256, smem>>>(x, out);
}

// round 5
// speedup vs baseline: 1.4998x; 1.1782x over previous
#include <cuda_runtime.h>
#include <math.h>

#define NQ 8
#define NS 256          // 2^8 amplitudes
#define DEPTH 200
#define BSZ 16384
#define NXF 64
#define NT 32           // batches per block in main kernel
#define NTP 33          // padded batch stride in shared
#define NBLK (BSZ/NT)   // 512 blocks

typedef unsigned long long ull;

// ---------------- device globals (no cudaMalloc allowed) ----------------
__device__ float4 g_uv[600 * 8];     // per layer, per qubit: (u.re,u.im,v.re,v.im) of RY(b)*RX(a)
__device__ float2 g_encphi[128];     // (cos(phi/2), sin(phi/2)) for the 2*64 encode phi angles
__device__ float2 g_v0[NS];          // U1 |0>
__device__ float2 g_U2T[NS * NS];    // [k][m] = (U2*Dcz)[m][k]
__device__ float2 g_U3T[NS * NS];    // [k][m] = (U3*Dcz)[m][k]

// ---------------- packed f32x2 helpers (Blackwell FFMA2 path) ----------------
__device__ __forceinline__ void ffma2(ull& d, ull a, ull b) {
    asm("fma.rn.f32x2 %0, %1, %2, %0;" : "+l"(d) : "l"(a), "l"(b));
}
__device__ __forceinline__ ull pack2(float lo, float hi) {
    ull r; asm("mov.b64 %0, {%1, %2};" : "=l"(r) : "f"(lo), "f"(hi)); return r;
}
__device__ __forceinline__ float2 unpack2(ull v) {
    float2 r; asm("mov.b64 {%0, %1}, %2;" : "=f"(r.x), "=f"(r.y) : "l"(v)); return r;
}

// ring-CZ parity sign for amplitude index n (qubit i <-> bit 7-i)
__device__ __forceinline__ float czsign(int n) {
    int par = __popc(n & (n >> 1)) + ((n & (n >> 7)) & 1);
    return (par & 1) ? -1.0f : 1.0f;
}

// ---------------- K0: angle tables (grid-strided) ----------------
__global__ void k_tables(const float* __restrict__ phi) {
    int tid = blockIdx.x * blockDim.x + threadIdx.x;
    int stride = gridDim.x * blockDim.x;
    for (int idx = tid; idx < 600 * 8; idx += stride) {
        int L = idx >> 3, q = idx & 7;
        int base, l;
        if (L < 200)      { base = 0;    l = L; }
        else if (L < 400) { base = 3264; l = L - 200; }
        else              { base = 6528; l = L - 400; }
        float a = phi[base + l * 16 + q];
        float b = phi[base + l * 16 + 8 + q];
        float ca, sa, cb, sb;
        sincosf(0.5f * a, &sa, &ca);
        sincosf(0.5f * b, &sb, &cb);
        g_uv[idx] = make_float4(ca * cb, sa * sb, ca * sb, -sa * cb);
    }
    for (int idx = tid; idx < 128; idx += stride) {
        int base = (idx < 64) ? 3200 : 6400;
        float p = phi[base + idx];
        float c, s;
        sincosf(0.5f * p, &s, &c);
        g_encphi[idx] = make_float2(c, s);
    }
}

// ---------------- K1: build v0, U2', U3' columns ----------------
// One warp per column; 8 amps/lane in registers. High-5 qubits via shfl_xor
// butterflies, low-3 via register permutes. No shared memory, no barriers.
__global__ void __launch_bounds__(256) k_build() {
    int gw = (blockIdx.x * blockDim.x + threadIdx.x) >> 5;   // global warp id
    if (gw >= 513) return;                                    // warp-uniform exit
    int lane = threadIdx.x & 31;

    int Lbase, col;
    bool lastCZ;
    float2* outp;
    float initv;
    if (gw < 256)      { Lbase = 200; lastCZ = true;  col = gw;       outp = &g_U2T[col * NS]; initv = czsign(col); }
    else if (gw < 512) { Lbase = 400; lastCZ = false; col = gw - 256; outp = &g_U3T[col * NS]; initv = czsign(col); }
    else               { Lbase = 0;   lastCZ = true;  col = 0;        outp = g_v0;             initv = 1.0f; }

    float2 amp[8];
    float  sgn[8];
    #pragma unroll
    for (int j = 0; j < 8; j++) {
        int n = lane * 8 + j;
        amp[j] = (n == col) ? make_float2(initv, 0.f) : make_float2(0.f, 0.f);
        sgn[j] = czsign(n);
    }

    for (int l = 0; l < DEPTH; l++) {
        const float4* uvL = &g_uv[(Lbase + l) * 8];
        // ---- lane-bit gates: q = 0..4  (bit p = 7-q, lane bit b = p-3) ----
        #pragma unroll
        for (int q = 0; q < 5; q++) {
            float4 uv = uvL[q];
            int b = 4 - q;
            int mybit = (lane >> b) & 1;
            float mai = mybit ? -uv.y : uv.y;
            float mbr = mybit ?  uv.z : -uv.z;
            ull Ap = pack2(uv.x, mai),  An = pack2(-mai, uv.x);
            ull Bp = pack2(mbr, uv.w),  Bn = pack2(-uv.w, mbr);
            #pragma unroll
            for (int j = 0; j < 8; j++) {
                float pr = __shfl_xor_sync(0xffffffffu, amp[j].x, 1 << b);
                float pi = __shfl_xor_sync(0xffffffffu, amp[j].y, 1 << b);
                ull acc = 0ull;
                ffma2(acc, pack2(amp[j].x, amp[j].x), Ap);
                ffma2(acc, pack2(amp[j].y, amp[j].y), An);
                ffma2(acc, pack2(pr, pr), Bp);
                ffma2(acc, pack2(pi, pi), Bn);
                amp[j] = unpack2(acc);
            }
        }
        // ---- local gates: q = 5,6,7 (bit p = 2,1,0 within the 8 local amps) ----
        #pragma unroll
        for (int q = 5; q < 8; q++) {
            float4 uv = uvL[q];
            int p = 7 - q;
            ull A00p = pack2( uv.x,  uv.y), A00n = pack2(-uv.y,  uv.x);
            ull A01p = pack2(-uv.z,  uv.w), A01n = pack2(-uv.w, -uv.z);
            ull A10p = pack2( uv.z,  uv.w), A10n = pack2(-uv.w,  uv.z);
            ull A11p = pack2( uv.x, -uv.y), A11n = pack2( uv.y,  uv.x);
            #pragma unroll
            for (int t = 0; t < 4; t++) {
                int lowm = (1 << p) - 1;
                int j0 = ((t & ~lowm) << 1) | (t & lowm);
                int j1 = j0 | (1 << p);
                float2 a0 = amp[j0], a1 = amp[j1];
                ull sx0 = pack2(a0.x, a0.x), sy0 = pack2(a0.y, a0.y);
                ull sx1 = pack2(a1.x, a1.x), sy1 = pack2(a1.y, a1.y);
                ull acc0 = 0ull, acc1 = 0ull;
                ffma2(acc0, sx0, A00p); ffma2(acc0, sy0, A00n);
                ffma2(acc0, sx1, A01p); ffma2(acc0, sy1, A01n);
                ffma2(acc1, sx0, A10p); ffma2(acc1, sy0, A10n);
                ffma2(acc1, sx1, A11p); ffma2(acc1, sy1, A11n);
                amp[j0] = unpack2(acc0);
                amp[j1] = unpack2(acc1);
            }
        }
        // ---- ring-CZ diagonal ----
        if ((l < DEPTH - 1) || lastCZ) {
            #pragma unroll
            for (int j = 0; j < 8; j++) { amp[j].x *= sgn[j]; amp[j].y *= sgn[j]; }
        }
    }
    // write column (each lane: 64B contiguous)
    float4* o4 = reinterpret_cast<float4*>(outp);
    #pragma unroll
    for (int jj = 0; jj < 4; jj++)
        o4[lane * 4 + jj] = make_float4(amp[2 * jj].x, amp[2 * jj].y,
                                        amp[2 * jj + 1].x, amp[2 * jj + 1].y);
}

// ---------------- K2: fused per-batch pipeline ----------------
__device__ __forceinline__ void su2_mul(float& Eur, float& Eui, float& Evr, float& Evi,
                                        float gur, float gui, float gvr, float gvi) {
    float ur = gur * Eur - gui * Eui - (gvr * Evr + gvi * Evi);
    float ui = gur * Eui + gui * Eur - (gvr * Evi - gvi * Evr);
    float vr = gvr * Eur - gvi * Eui + (gur * Evr + gui * Evi);
    float vi = gvr * Eui + gvi * Eur + (gur * Evi - gui * Evr);
    Eur = ur; Eui = ui; Evr = vr; Evi = vi;
}

__device__ __forceinline__ float4 compose_E(const float* __restrict__ x, int bg,
                                            int xoff, int enc, int i) {
    float Eur = 1.f, Eui = 0.f, Evr = 0.f, Evi = 0.f;
    #pragma unroll
    for (int j = 0; j < 4; j++) {
        float2 p0 = g_encphi[enc * 64 + 8 * i + 2 * j];
        float2 p1 = g_encphi[enc * 64 + 8 * i + 2 * j + 1];
        float xv = x[(size_t)bg * NXF + xoff + 4 * i + j];
        float sx, cx;
        sincosf(0.5f * xv, &sx, &cx);
        if ((j & 1) == 0) {
            su2_mul(Eur, Eui, Evr, Evi, p0.x, 0.f, p0.y, 0.f);   // RY(p0)
            su2_mul(Eur, Eui, Evr, Evi, cx, 0.f, 0.f, -sx);      // RX(x)
            su2_mul(Eur, Eui, Evr, Evi, p1.x, 0.f, p1.y, 0.f);   // RY(p1)
        } else {
            su2_mul(Eur, Eui, Evr, Evi, p0.x, 0.f, 0.f, -p0.y);  // RX(p0)
            su2_mul(Eur, Eui, Evr, Evi, cx, 0.f, sx, 0.f);       // RY(x)
            su2_mul(Eur, Eui, Evr, Evi, p1.x, 0.f, 0.f, -p1.y);  // RX(p1)
        }
    }
    return make_float4(Eur, Eui, Evr, Evi);
}

__device__ __forceinline__ void apply_gates(float2* sPsi, const float4* sE, int tid) {
    #pragma unroll
    for (int q = 0; q < 8; q++) {
        int p = 7 - q;
        int low = (1 << p) - 1;
        #pragma unroll
        for (int it = 0; it < (128 * NT) / 256; it++) {  // 16
            int task = tid + it * 256;
            int b = task & (NT - 1);
            int pr = task >> 5;
            int n0 = ((pr & ~low) << 1) | (pr & low);
            int n1 = n0 | (1 << p);
            float4 E = sE[q * NT + b];
            float2 a0 = sPsi[n0 * NTP + b];
            float2 a1 = sPsi[n1 * NTP + b];
            float2 b0, b1;
            b0.x = E.x * a0.x - E.y * a0.y - (E.z * a1.x + E.w * a1.y);
            b0.y = E.x * a0.y + E.y * a0.x - (E.z * a1.y - E.w * a1.x);
            b1.x = E.z * a0.x - E.w * a0.y + (E.x * a1.x + E.y * a1.y);
            b1.y = E.z * a0.y + E.w * a0.x + (E.x * a1.y - E.y * a1.x);
            sPsi[n0 * NTP + b] = b0;
            sPsi[n1 * NTP + b] = b1;
        }
        __syncthreads();
    }
}

// in-place complex GEMM, packed f32x2 FMAs, ping-pong A staging (1 barrier/kc):
//   sPsi[m][b] = sum_k AT[k][m] * sPsi[k][b]
__device__ __forceinline__ void do_gemm(float2* sPsi, float2* sA2,
                                        const float2* __restrict__ AT,
                                        float2 pre[8],
                                        int tid, int lane, int warp) {
    int mh = warp >> 2;            // m-half:   m = mh*128 + lane*4 + rr
    int bo = warp & 3;             // b-octet:  b = bo*8 + j
    int mbase = mh * 128 + lane * 4;
    ull acc[4][8];
    #pragma unroll
    for (int r = 0; r < 4; r++)
        #pragma unroll
        for (int j = 0; j < 8; j++) acc[r][j] = 0ull;

    for (int kc = 0; kc < 32; kc++) {
        float2* buf = sA2 + (kc & 1) * 2048;
        #pragma unroll
        for (int r = 0; r < 8; r++) buf[tid + r * 256] = pre[r];
        if (kc + 1 < 32) {
            #pragma unroll
            for (int r = 0; r < 8; r++) pre[r] = AT[(kc + 1) * 2048 + tid + r * 256];
        }
        __syncthreads();
        #pragma unroll
        for (int kk = 0; kk < 8; kk++) {
            int k = kc * 8 + kk;
            float4 a01 = *reinterpret_cast<const float4*>(&buf[kk * 256 + mbase]);
            float4 a23 = *reinterpret_cast<const float4*>(&buf[kk * 256 + mbase + 2]);
            ull ap[4], as_[4];
            ap[0] = pack2(a01.x, a01.y); as_[0] = pack2(a01.y, a01.x);
            ap[1] = pack2(a01.z, a01.w); as_[1] = pack2(a01.w, a01.z);
            ap[2] = pack2(a23.x, a23.y); as_[2] = pack2(a23.y, a23.x);
            ap[3] = pack2(a23.z, a23.w); as_[3] = pack2(a23.w, a23.z);
            #pragma unroll
            for (int j = 0; j < 8; j++) {
                float2 bv = sPsi[k * NTP + bo * 8 + j];
                ull Br = pack2(bv.x, bv.x);
                ull Bn = pack2(-bv.y, bv.y);
                #pragma unroll
                for (int r = 0; r < 4; r++) {
                    ffma2(acc[r][j], ap[r], Br);    // (a.r, a.i) * (b.r, b.r)
                    ffma2(acc[r][j], as_[r], Bn);   // (a.i, a.r) * (-b.i, b.i)
                }
            }
        }
    }
    __syncthreads();  // all reads of sPsi done before overwrite
    #pragma unroll
    for (int r = 0; r < 4; r++)
        #pragma unroll
        for (int j = 0; j < 8; j++)
            *reinterpret_cast<ull*>(&sPsi[(mbase + r) * NTP + bo * 8 + j]) = acc[r][j];
    __syncthreads();
}

__global__ void __launch_bounds__(256, 2) k_main(const float* __restrict__ x,
                                                 float* __restrict__ out) {
    extern __shared__ float smraw[];
    float2* sPsi = (float2*)smraw;              // NS * NTP           (67584 B)
    float2* sA2  = sPsi + NS * NTP;             // 2 x 2048 float2    (32768 B)
    float4* sE   = (float4*)(sA2 + 2 * 2048);   // 8 * NT float4      ( 4096 B)

    int tid = threadIdx.x;
    int lane = tid & 31, warp = tid >> 5;       // 8 warps
    int bbase = blockIdx.x * NT;

    // ---- prefetch first A-chunk of U2 (hidden behind encode compute) ----
    float2 pre[8];
    #pragma unroll
    for (int r = 0; r < 8; r++) pre[r] = g_U2T[tid + r * 256];

    // ---- E1 compose: tid -> (b = tid&31, i = tid>>5) ----
    {
        int b = tid & (NT - 1), i = tid >> 5;
        sE[i * NT + b] = compose_E(x, bbase + b, 0, 0, i);
    }
    // ---- init Psi = v0 (broadcast over batches) ----
    for (int idx = tid; idx < NS * NT; idx += 256) {
        int b = idx & (NT - 1), amp = idx >> 5;
        sPsi[amp * NTP + b] = g_v0[amp];
    }
    __syncthreads();

    apply_gates(sPsi, sE, tid);                 // encode 1 (CZ folded into U2')
    do_gemm(sPsi, sA2, g_U2T, pre, tid, lane, warp);

    // ---- prefetch first A-chunk of U3, then E2 compose ----
    #pragma unroll
    for (int r = 0; r < 8; r++) pre[r] = g_U3T[tid + r * 256];
    {
        int b = tid & (NT - 1), i = tid >> 5;
        sE[i * NT + b] = compose_E(x, bbase + b, 32, 1, i);
    }
    __syncthreads();

    apply_gates(sPsi, sE, tid);                 // encode 2 (CZ folded into U3')
    do_gemm(sPsi, sA2, g_U3T, pre, tid, lane, warp);

    // ---- measurement: warp w handles batches w*4..w*4+3 ----
    for (int j = 0; j < 4; j++) {
        int b = warp * 4 + j;
        float sums[8];
        #pragma unroll
        for (int k = 0; k < 8; k++) sums[k] = 0.f;
        #pragma unroll
        for (int r = 0; r < 8; r++) {
            int m = lane + 32 * r;
            float2 ps = sPsi[m * NTP + b];
            float p2 = ps.x * ps.x + ps.y * ps.y;
            sums[4] += (m & 128) ? -p2 : p2;   // Z q0
            sums[5] += (m & 64)  ? -p2 : p2;   // Z q1
            sums[6] += (m & 32)  ? -p2 : p2;   // Z q2
            sums[7] += (m & 16)  ? -p2 : p2;   // Z q3
            float2 q0 = sPsi[(m ^ 128) * NTP + b];
            sums[0] += ps.x * q0.x + ps.y * q0.y;   // X q0
            float2 q1 = sPsi[(m ^ 64) * NTP + b];
            sums[1] += ps.x * q1.x + ps.y * q1.y;   // X q1
            float2 q2 = sPsi[(m ^ 32) * NTP + b];
            sums[2] += ps.x * q2.x + ps.y * q2.y;   // X q2
            float2 q3 = sPsi[(m ^ 16) * NTP + b];
            sums[3] += ps.x * q3.x + ps.y * q3.y;   // X q3
        }
        #pragma unroll
        for (int off = 16; off; off >>= 1) {
            #pragma unroll
            for (int k = 0; k < 8; k++)
                sums[k] += __shfl_xor_sync(0xffffffffu, sums[k], off);
        }
        if (lane < 8) out[(size_t)(bbase + b) * 8 + lane] = sums[lane];
    }
}

// ---------------- launch ----------------
extern "C" void kernel_launch(void* const* d_in, const int* in_sizes, int n_in,
                              void* d_out, int out_size) {
    const float* x   = (const float*)d_in[0];
    const float* phi = (const float*)d_in[1];
    float* out = (float*)d_out;

    const size_t smem = (size_t)(NS * NTP) * sizeof(float2)   // 67584
                      + (size_t)(2 * 2048) * sizeof(float2)   // 32768
                      + (size_t)(8 * NT) * sizeof(float4);    //  4096
    cudaFuncSetAttribute(k_main, cudaFuncAttributeMaxDynamicSharedMemorySize, (int)smem);

    k_tables<<<20, 256>>>(phi);
    k_build<<<65, 256>>>();
    k_main<<<NBLK, 256, smem>>>(x, out);
}